// round 8
// baseline (speedup 1.0000x reference)
#include <cuda_runtime.h>
#include <cstdint>
#include <math.h>

// Problem shape (fixed): N=16, T=256, U=128, V=256, blank = V-1.
#define N_  16
#define T_  256
#define U_  128
#define V_  256
#define DD  383           // anti-diagonals d = 0..382
#define DD_PAD 400
#define NEGF (-1e30f)

#define NCTAS   148
#define NUNITS  280       // gather units (128 threads each)
#define NTASKS  (N_ * 384)  // row-tasks: r in [1,384] x n in [0,16)

// Scratch (allocation-free rule: __device__ globals, zero-initialized).
// SHIFTED diagonal-major layout: blank(n,t,u) at [n][t+u+1][u]; emit(n,t,u) at
// [n][t+u+1][u+1]. Unwritten slots stay 0 and only combine with NEG alphas.
__device__ __align__(16) float g_blank[N_ * DD_PAD * U_];
__device__ __align__(16) float g_emit [N_ * DD_PAD * U_];
__device__ float    g_cost[N_];
// Epoch flags: each is incremented EXACTLY ONCE per kernel launch, so across
// graph replays "flag >= ep" (ep = this launch's epoch) is a correct ready test
// with no reset step.
__device__ unsigned g_rowflag [N_ * DD_PAD];   // [n*DD_PAD + r]
__device__ unsigned g_costflag[N_];
__device__ unsigned g_dpep    [N_];

// ---- sync helpers ----------------------------------------------------------
__device__ __forceinline__ unsigned ld_acq_u32(const unsigned* p) {
    unsigned v;
    asm volatile("ld.acquire.gpu.global.u32 %0, [%1];" : "=r"(v) : "l"(p) : "memory");
    return v;
}
__device__ __forceinline__ uint4 ld_acq_v4(const unsigned* p) {
    uint4 v;
    asm volatile("ld.acquire.gpu.global.v4.u32 {%0,%1,%2,%3}, [%4];"
                 : "=r"(v.x), "=r"(v.y), "=r"(v.z), "=r"(v.w) : "l"(p) : "memory");
    return v;
}
__device__ __forceinline__ void red_rel_add1(unsigned* p) {
    asm volatile("red.release.gpu.global.add.u32 [%0], 1;" :: "l"(p) : "memory");
}
__device__ __forceinline__ bool ok4(uint4 f, unsigned ep) {
    return f.x >= ep && f.y >= ep && f.z >= ep && f.w >= ep;
}

// ---------------------------------------------------------------------------
// Gather unit: 128 threads, processes row-tasks unit, unit+280, ... in
// 4-task super-iterations (8 front-batched scattered loads per thread).
// Task t -> (r = 1 + t/16, n = t%16). After a super-iteration's stores are
// globally visible, the leader bumps the per-(n,r) epoch flags.
// ---------------------------------------------------------------------------
__device__ void gather_unit(const float* __restrict__ lp,
                            const int*   __restrict__ labels,
                            int unit, int lt, int barid)
{
    const int c = lt;                       // column 0..127
    for (int s = 0; s < 6; ++s) {
        float vb[4], ve[4];
#pragma unroll
        for (int j = 0; j < 4; ++j) {
            int t  = unit + NUNITS * (4 * s + j);
            int tv = t < NTASKS ? t : NTASKS - 1;
            int r  = 1 + (tv >> 4);
            int n  = tv & 15;
            int tb = r - 1 - c;                       // blank(t=tb, u=c)
            int te = r - c;                           // emit (t=te, u=c-1)
            int tbc = tb < 0 ? 0 : (tb > T_ - 1 ? T_ - 1 : tb);
            int tec = te < 0 ? 0 : (te > T_ - 1 ? T_ - 1 : te);
            int lbl = (c >= 1) ? __ldg(&labels[n * (U_ - 1) + (c - 1)]) : 0;
            vb[j] = __ldcs(lp + ((((size_t)n * T_ + tbc) * U_ + c) * V_) + (V_ - 1));
            ve[j] = __ldcs(lp + ((((size_t)n * T_ + tec) * U_ + (c - (c >= 1))) * V_) + lbl);
        }
#pragma unroll
        for (int j = 0; j < 4; ++j) {
            int t = unit + NUNITS * (4 * s + j);
            if (t >= NTASKS) continue;
            int r = 1 + (t >> 4);
            int n = t & 15;
            int tb = r - 1 - c;
            int te = r - c;
            size_t rowbase = ((size_t)n * DD_PAD + r) * U_;
            if (tb >= 0 && tb < T_)           g_blank[rowbase + c] = vb[j];
            if (c >= 1 && te >= 0 && te < T_) g_emit [rowbase + c] = ve[j];
        }
        __threadfence();
        asm volatile("bar.sync %0, %1;" :: "r"(barid), "r"(128) : "memory");
        if (lt == 0) {
#pragma unroll
            for (int j = 0; j < 4; ++j) {
                int t = unit + NUNITS * (4 * s + j);
                if (t >= NTASKS) continue;
                red_rel_add1(&g_rowflag[(t & 15) * DD_PAD + 1 + (t >> 4)]);
            }
        }
    }
}

// ---------------------------------------------------------------------------
// DP warp: one warp, example n, 4 u-columns per thread, cp.async 16-slot ring,
// flag-gated row issue. Ends with cost write; CTA0 lane0 also does the mean.
// ---------------------------------------------------------------------------
__device__ __forceinline__ float lse2(float a, float b) {
    float mx = fmaxf(a, b);
    float mn = fminf(a, b);
    return mx + 0.6931471805599453f *
                __log2f(1.0f + exp2f((mn - mx) * 1.4426950408889634f));
}

#define DP_STEP(bv, ev, dcur)                                                 \
    {                                                                         \
        float la = __shfl_up_sync(0xffffffffu, a3, 1);                        \
        float l0 = (tx == 0) ? NEGF : la;                                     \
        float n0 = lse2(a0 + (bv).x, l0 + (ev).x);                            \
        float n1 = lse2(a1 + (bv).y, a0 + (ev).y);                            \
        float n2 = lse2(a2 + (bv).z, a1 + (ev).z);                            \
        float n3 = lse2(a3 + (bv).w, a2 + (ev).w);                            \
        a0 = n0; a1 = n1; a2 = n2; a3 = n3;                                   \
        if ((dcur) == target && cap)                                          \
            saved = (ci == 0) ? n0 : (ci == 1) ? n1 : (ci == 2) ? n2 : n3;    \
    }

#define ISSUE_ROW(rr)                                                         \
    {                                                                         \
        int _rrc = (rr) < (DD_PAD - 1) ? (rr) : (DD_PAD - 1);                 \
        unsigned _slot = ((unsigned)(rr) & 15u) * (U_ * 4u) + lane_off;       \
        const float* _gb = bl + (size_t)_rrc * U_ + 4 * tx;                   \
        const float* _ge = em + (size_t)_rrc * U_ + 4 * tx;                   \
        asm volatile("cp.async.ca.shared.global [%0], [%1], 16;"              \
                     :: "r"(sb_base + _slot), "l"(_gb));                      \
        asm volatile("cp.async.ca.shared.global [%0], [%1], 16;"              \
                     :: "r"(se_base + _slot), "l"(_ge));                      \
    }

#define DP_PAIR(p)                                                            \
    {                                                                         \
        asm volatile("cp.async.wait_group 6;" ::: "memory");                  \
        ISSUE_ROW(2 * (p) + 15);                                              \
        ISSUE_ROW(2 * (p) + 16);                                              \
        asm volatile("cp.async.commit_group;" ::: "memory");                  \
        const int _d1 = 2 * (p) + 1;                                          \
        {                                                                     \
            const int _s = _d1 & 15;                                          \
            float4 b = *(const float4*)&sb[_s * U_ + 4 * tx];                 \
            float4 e = *(const float4*)&se[_s * U_ + 4 * tx];                 \
            DP_STEP(b, e, _d1);                                               \
        }                                                                     \
        {                                                                     \
            const int _d2 = _d1 + 1;                                          \
            const int _s = _d2 & 15;                                          \
            float4 b = *(const float4*)&sb[_s * U_ + 4 * tx];                 \
            float4 e = *(const float4*)&se[_s * U_ + 4 * tx];                 \
            DP_STEP(b, e, _d2);                                               \
        }                                                                     \
    }

__device__ void dp_warp(const int* __restrict__ lengths,
                        const int* __restrict__ label_lengths,
                        int n, int tx, float* sb, float* se, float* out)
{
    // Per-launch epoch (monotonic counter; +1 per launch).
    unsigned ep;
    if (tx == 0) ep = atomicAdd(&g_dpep[n], 1u) + 1u;
    ep = __shfl_sync(0xffffffffu, ep, 0);

    const unsigned* flg = g_rowflag + n * DD_PAD;
    const float* __restrict__ bl = g_blank + (size_t)n * DD_PAD * U_;
    const float* __restrict__ em = g_emit  + (size_t)n * DD_PAD * U_;

    const int t_idx  = lengths[n] - 1;
    const int u_idx  = label_lengths[n];
    const int target = t_idx + u_idx;

    float a0 = (tx == 0) ? 0.0f : NEGF;
    float a1 = NEGF, a2 = NEGF, a3 = NEGF;
    float saved = 0.0f;
    const bool cap = (tx == (u_idx >> 2));
    const int  ci  = u_idx & 3;

    const unsigned sb_base = (unsigned)__cvta_generic_to_shared(sb);
    const unsigned se_base = (unsigned)__cvta_generic_to_shared(se);
    const unsigned lane_off = 16u * (unsigned)tx;

    // Initial: wait for rows 1..16 (lane-parallel spins).
    if (tx < 16) {
        while (ld_acq_u32(flg + (tx + 1)) < ep) __nanosleep(64);
    }
    __syncwarp();

    // Prologue: issue rows 1..14 (7 commit groups).
#pragma unroll
    for (int q = 0; q < 7; ++q) {
        ISSUE_ROW(2 * q + 1);
        ISSUE_ROW(2 * q + 2);
        asm volatile("cp.async.commit_group;" ::: "memory");
    }

    // Flag pipeline: group g covers pairs 4g..4g+3 (issues rows 8g+15..8g+22);
    // check covers rows 8g+12..8g+23 (16B-aligned v4 loads), prefetched one
    // group ahead so the L2 latency is off the critical path.
    uint4 f0 = ld_acq_v4(flg + 12), f1 = ld_acq_v4(flg + 16), f2 = ld_acq_v4(flg + 20);

    for (int g = 0; g < 45; ++g) {
        while (!(ok4(f0, ep) && ok4(f1, ep) && ok4(f2, ep))) {
            __nanosleep(64);
            int base = 8 * g + 12;
            f0 = ld_acq_v4(flg + base); f1 = ld_acq_v4(flg + base + 4); f2 = ld_acq_v4(flg + base + 8);
        }
        int nbase = (g < 44) ? (8 * g + 20) : 372;   // g=44 prefetches tail block
        uint4 nf0 = ld_acq_v4(flg + nbase);
        uint4 nf1 = ld_acq_v4(flg + nbase + 4);
        uint4 nf2 = ld_acq_v4(flg + nbase + 8);

        const int p0 = 4 * g;
        DP_PAIR(p0); DP_PAIR(p0 + 1); DP_PAIR(p0 + 2); DP_PAIR(p0 + 3);

        f0 = nf0; f1 = nf1; f2 = nf2;
    }

    // Tail: confirm rows 372..383 + row 384, then pairs 180..190 checkless.
    while (!(ok4(f0, ep) && ok4(f1, ep) && ok4(f2, ep))) {
        __nanosleep(64);
        f0 = ld_acq_v4(flg + 372); f1 = ld_acq_v4(flg + 376); f2 = ld_acq_v4(flg + 380);
    }
    while (ld_acq_u32(flg + 384) < ep) __nanosleep(64);

    for (int p = 180; p < 191; ++p) { DP_PAIR(p); }

    if (cap) {
        float bfin = bl[(size_t)(target + 1) * U_ + u_idx];  // blank(t_idx, u_idx)
        g_cost[n] = -(saved + bfin);
        __threadfence();
        red_rel_add1(&g_costflag[n]);
    }

    // Finalize (CTA for n==0, lane 0): deterministic serial mean.
    if (n == 0 && tx == 0) {
        float s = 0.0f;
#pragma unroll
        for (int i = 0; i < N_; ++i) {
            while (ld_acq_u32(&g_costflag[i]) < ep) __nanosleep(128);
            s += __ldcg(&g_cost[i]);
        }
        out[0] = s * (1.0f / N_);
    }
}

// ---------------------------------------------------------------------------
// Fused persistent kernel.
//   CTA 0..15  : warp 0 = DP(example = ctaid); warps 4..7 = gather unit ctaid.
//   CTA 16..147: warps 0..3 = gather unit 2c-16; warps 4..7 = unit 2c-15.
// Gather CTAs never wait on DP -> progress (and thus completion) is
// unconditional; DP only ever waits on gather flags.
// ---------------------------------------------------------------------------
__global__ void __launch_bounds__(256) fused_kernel(const float* __restrict__ lp,
                                                    const int*   __restrict__ labels,
                                                    const int*   __restrict__ lengths,
                                                    const int*   __restrict__ label_lengths,
                                                    float* __restrict__ out)
{
    __shared__ __align__(16) float sb[16 * U_];
    __shared__ __align__(16) float se[16 * U_];

    const int cta  = blockIdx.x;
    const int tid  = threadIdx.x;
    const int half = tid >> 7;           // 0 or 1
    const int lt   = tid & 127;

    if (cta < N_) {
        if (tid < 32) {
            dp_warp(lengths, label_lengths, cta, tid, sb, se, out);
        } else if (half == 1) {
            gather_unit(lp, labels, cta, lt, /*barid=*/1);
        }
        // warps 1..3 idle
    } else {
        int unit = 2 * cta - 16 + half;  // 16..279
        gather_unit(lp, labels, unit, lt, /*barid=*/1 + half);
    }
}

// ---------------------------------------------------------------------------
extern "C" void kernel_launch(void* const* d_in, const int* in_sizes, int n_in,
                              void* d_out, int out_size)
{
    const float* log_probs     = (const float*)d_in[0];
    const int*   labels        = (const int*)  d_in[1];
    const int*   lengths       = (const int*)  d_in[2];
    const int*   label_lengths = (const int*)  d_in[3];
    float*       out           = (float*)d_out;

    fused_kernel<<<NCTAS, 256>>>(log_probs, labels, lengths, label_lengths, out);
}